// round 1
// baseline (speedup 1.0000x reference)
#include <cuda_runtime.h>
#include <math.h>

// ---------------------------------------------------------------------------
// Swin block: B=32, H=W=128, C=128, WS=2, SS=1, NH=8, HD=16
// T = B*H*W = 524288 tokens, NWIN = B*(H/2)*(W/2) = 131072 windows (4 tok each)
// ---------------------------------------------------------------------------

#define TOK   524288
#define NWIN  131072

// scratch (device globals; allocation-free per harness rules)
__device__ float g_aw [(size_t)TOK * 128]; // LN1 output, window-ordered
__device__ float g_qkv[(size_t)TOK * 384]; // qkv, window-ordered
__device__ float g_o  [(size_t)TOK * 128]; // attention out, window-ordered
__device__ float g_h2 [(size_t)TOK * 128]; // x + attn-proj, original order
__device__ float g_ln2[(size_t)TOK * 128]; // LN2 output
__device__ float g_m1 [(size_t)TOK * 256]; // mlp hidden

// packed f32x2 helpers (sm_100+)
#define PACK2(u, x, y) asm("mov.b64 %0, {%1,%2};" : "=l"(u) : "f"(x), "f"(y))
#define FMA2(d, a, b)  asm("fma.rn.f32x2 %0, %1, %2, %0;" : "+l"(d) : "l"(a), "l"(b))
#define UNPK(x, y, u)  asm("mov.b64 {%0,%1}, %2;" : "=f"(x), "=f"(y) : "l"(u))

// window-ordered token r -> original token index (handles cyclic shift by 1)
__device__ __forceinline__ int orig_of(int r) {
    int win = r >> 2, s = r & 3;
    int b  = win >> 12;          // / 4096
    int w  = win & 4095;
    int wh = w >> 6, ww = w & 63;
    int ii = ((wh << 1) + (s >> 1) + 1) & 127;
    int jj = ((ww << 1) + (s & 1) + 1) & 127;
    return (b << 14) + (ii << 7) + jj;
}

// ---------------------------------------------------------------------------
// LayerNorm over C=128; one warp per token. GATHER=true reads rows through the
// shift+window-partition mapping and writes window-ordered rows.
// ---------------------------------------------------------------------------
template <bool GATHER>
__global__ __launch_bounds__(256) void ln_kernel(
    const float* __restrict__ in, const float* __restrict__ gamma,
    const float* __restrict__ beta, float* __restrict__ out)
{
    int row  = (blockIdx.x * 256 + threadIdx.x) >> 5;
    int lane = threadIdx.x & 31;
    int src  = GATHER ? orig_of(row) : row;

    float4 v = *(const float4*)(in + (size_t)src * 128 + lane * 4);
    float s = v.x + v.y + v.z + v.w;
    float q = v.x * v.x + v.y * v.y + v.z * v.z + v.w * v.w;
#pragma unroll
    for (int off = 16; off; off >>= 1) {
        s += __shfl_xor_sync(0xffffffffu, s, off);
        q += __shfl_xor_sync(0xffffffffu, q, off);
    }
    float mean = s * (1.0f / 128.0f);
    float var  = q * (1.0f / 128.0f) - mean * mean;
    float rstd = rsqrtf(var + 1e-5f);

    float4 g = *(const float4*)(gamma + lane * 4);
    float4 b = *(const float4*)(beta  + lane * 4);
    float4 o;
    o.x = (v.x - mean) * rstd * g.x + b.x;
    o.y = (v.y - mean) * rstd * g.y + b.y;
    o.z = (v.z - mean) * rstd * g.z + b.z;
    o.w = (v.w - mean) * rstd * g.w + b.w;
    *(float4*)(out + (size_t)row * 128 + lane * 4) = o;
}

// ---------------------------------------------------------------------------
// 64x64-tile SGEMM (M = TOK, small N/K), 256 threads, 4x4 micro-tile per
// thread, f32x2 packed FMA inner loop. Epilogues cover all four GEMMs.
// ---------------------------------------------------------------------------
enum { EPI_NONE = 0, EPI_PROJ = 1, EPI_GELU = 2, EPI_SKIP = 3 };

template <int K, int N, int EPI>
__global__ __launch_bounds__(256) void gemm64(
    const float* __restrict__ A, const float* __restrict__ Bw,
    const float* __restrict__ bias, const float* __restrict__ skip,
    float* __restrict__ out)
{
    __shared__ float AsT[32][68]; // transposed A chunk, padded (16B-aligned rows)
    __shared__ float Bs [32][64];

    const int tid = threadIdx.x;
    const int tx = tid & 15, ty = tid >> 4;
    const int r0 = ty << 2, c0 = tx << 2;
    const int rowBase = blockIdx.y << 6;
    const int n0      = blockIdx.x << 6;
    const int lr = tid >> 2, lk = (tid & 3) << 3;  // A loader: row, k-offset
    const int bk = tid >> 3, bn = (tid & 7) << 3;  // B loader: k-row, n-offset

    unsigned long long acc[4][2];
#pragma unroll
    for (int i = 0; i < 4; i++) { acc[i][0] = 0ull; acc[i][1] = 0ull; }

    const float* Arow = A  + (size_t)(rowBase + lr) * K + lk;
    const float* Brow = Bw + (size_t)bk * N + n0 + bn;

    for (int kc = 0; kc < K; kc += 32) {
        float4 a0 = *(const float4*)(Arow + kc);
        float4 a1 = *(const float4*)(Arow + kc + 4);
        float4 b0 = *(const float4*)(Brow + (size_t)kc * N);
        float4 b1 = *(const float4*)(Brow + (size_t)kc * N + 4);

        AsT[lk + 0][lr] = a0.x; AsT[lk + 1][lr] = a0.y;
        AsT[lk + 2][lr] = a0.z; AsT[lk + 3][lr] = a0.w;
        AsT[lk + 4][lr] = a1.x; AsT[lk + 5][lr] = a1.y;
        AsT[lk + 6][lr] = a1.z; AsT[lk + 7][lr] = a1.w;
        *(float4*)&Bs[bk][bn]     = b0;
        *(float4*)&Bs[bk][bn + 4] = b1;
        __syncthreads();

#pragma unroll
        for (int kk = 0; kk < 32; kk++) {
            float4 av = *(const float4*)&AsT[kk][r0];
            float4 bv = *(const float4*)&Bs[kk][c0];
            unsigned long long bl, bh, ad;
            PACK2(bl, bv.x, bv.y);
            PACK2(bh, bv.z, bv.w);
            PACK2(ad, av.x, av.x); FMA2(acc[0][0], ad, bl); FMA2(acc[0][1], ad, bh);
            PACK2(ad, av.y, av.y); FMA2(acc[1][0], ad, bl); FMA2(acc[1][1], ad, bh);
            PACK2(ad, av.z, av.z); FMA2(acc[2][0], ad, bl); FMA2(acc[2][1], ad, bh);
            PACK2(ad, av.w, av.w); FMA2(acc[3][0], ad, bl); FMA2(acc[3][1], ad, bh);
        }
        __syncthreads();
    }

#pragma unroll
    for (int i = 0; i < 4; i++) {
        int gr = rowBase + r0 + i;
        size_t outRow = (EPI == EPI_PROJ) ? (size_t)orig_of(gr) : (size_t)gr;
        float v[4];
        UNPK(v[0], v[1], acc[i][0]);
        UNPK(v[2], v[3], acc[i][1]);
#pragma unroll
        for (int j = 0; j < 4; j++) {
            int col = n0 + c0 + j;
            float x = v[j] + bias[col];
            if (EPI == EPI_GELU) x = x * normcdff(x);           // exact GELU
            if (EPI == EPI_PROJ) x += skip[outRow * N + col];   // + residual x
            if (EPI == EPI_SKIP) x += skip[outRow * N + col];   // + residual h2
            out[outRow * (size_t)N + col] = x;
        }
    }
}

// ---------------------------------------------------------------------------
// Windowed attention: one warp per window; lane = head*4 + query_token.
// q,k,v read from g_qkv (col = three*128 + h*16 + d). Mask & rpb analytic.
// ---------------------------------------------------------------------------
__global__ __launch_bounds__(256) void attn_kernel(
    const float* __restrict__ qkv, const float* __restrict__ rpb,
    float* __restrict__ o)
{
    int warp = (blockIdx.x * 256 + threadIdx.x) >> 5;
    int lane = threadIdx.x & 31;
    int h = lane >> 2, i = lane & 3;

    int w  = warp & 4095;
    bool mr = ((w >> 6) == 63);   // last window row -> mask active in h-dim
    bool mc = ((w & 63) == 63);   // last window col -> mask active in w-dim

    const float* base = qkv + (size_t)warp * (4 * 384);

    float q[16];
    const float* qp = base + i * 384 + h * 16;
#pragma unroll
    for (int d4 = 0; d4 < 4; d4++) {
        float4 t = *(const float4*)(qp + d4 * 4);
        q[d4 * 4 + 0] = t.x; q[d4 * 4 + 1] = t.y;
        q[d4 * 4 + 2] = t.z; q[d4 * 4 + 3] = t.w;
    }

    int dy1 = i >> 1, dx1 = i & 1;
    float s[4];
#pragma unroll
    for (int j = 0; j < 4; j++) {
        const float* kp = base + j * 384 + 128 + h * 16;
        float acc = 0.0f;
#pragma unroll
        for (int d4 = 0; d4 < 4; d4++) {
            float4 t = *(const float4*)(kp + d4 * 4);
            acc += q[d4 * 4 + 0] * t.x + q[d4 * 4 + 1] * t.y
                 + q[d4 * 4 + 2] * t.z + q[d4 * 4 + 3] * t.w;
        }
        int dy2 = j >> 1, dx2 = j & 1;
        bool ok = (!mr || dy1 == dy2) && (!mc || dx1 == dx2);
        int rpi = (dy1 - dy2 + 1) * 3 + (dx1 - dx2 + 1);
        s[j] = acc * 0.25f + rpb[rpi * 8 + h] + (ok ? 0.0f : -100.0f);
    }

    float mx = fmaxf(fmaxf(s[0], s[1]), fmaxf(s[2], s[3]));
    float p[4], sum = 0.0f;
#pragma unroll
    for (int j = 0; j < 4; j++) { p[j] = expf(s[j] - mx); sum += p[j]; }
    float inv = 1.0f / sum;

    float ov[16];
#pragma unroll
    for (int d = 0; d < 16; d++) ov[d] = 0.0f;
#pragma unroll
    for (int j = 0; j < 4; j++) {
        const float* vp = base + j * 384 + 256 + h * 16;
        float pj = p[j] * inv;
#pragma unroll
        for (int d4 = 0; d4 < 4; d4++) {
            float4 t = *(const float4*)(vp + d4 * 4);
            ov[d4 * 4 + 0] += pj * t.x; ov[d4 * 4 + 1] += pj * t.y;
            ov[d4 * 4 + 2] += pj * t.z; ov[d4 * 4 + 3] += pj * t.w;
        }
    }

    float* op = o + (size_t)(warp * 4 + i) * 128 + h * 16;
#pragma unroll
    for (int d4 = 0; d4 < 4; d4++) {
        float4 t;
        t.x = ov[d4 * 4 + 0]; t.y = ov[d4 * 4 + 1];
        t.z = ov[d4 * 4 + 2]; t.w = ov[d4 * 4 + 3];
        *(float4*)(op + d4 * 4) = t;
    }
}

// ---------------------------------------------------------------------------
extern "C" void kernel_launch(void* const* d_in, const int* in_sizes, int n_in,
                              void* d_out, int out_size)
{
    const float* x      = (const float*)d_in[0];
    const float* qkv_w  = (const float*)d_in[1];
    const float* qkv_b  = (const float*)d_in[2];
    const float* proj_w = (const float*)d_in[3];
    const float* proj_b = (const float*)d_in[4];
    const float* rpb    = (const float*)d_in[5];
    const float* g1     = (const float*)d_in[6];
    const float* b1     = (const float*)d_in[7];
    const float* g2     = (const float*)d_in[8];
    const float* b2     = (const float*)d_in[9];
    const float* w1     = (const float*)d_in[10];
    const float* bb1    = (const float*)d_in[11];
    const float* w2     = (const float*)d_in[12];
    const float* bb2    = (const float*)d_in[13];
    float* out = (float*)d_out;

    float *aw, *qkv, *o, *h2, *ln2, *m1;
    cudaGetSymbolAddress((void**)&aw,  g_aw);
    cudaGetSymbolAddress((void**)&qkv, g_qkv);
    cudaGetSymbolAddress((void**)&o,   g_o);
    cudaGetSymbolAddress((void**)&h2,  g_h2);
    cudaGetSymbolAddress((void**)&ln2, g_ln2);
    cudaGetSymbolAddress((void**)&m1,  g_m1);

    const int MT = TOK / 64; // 8192 M-tiles

    // 1) LN1 fused with shift + window-partition gather
    ln_kernel<true><<<TOK / 8, 256>>>(x, g1, b1, aw);
    // 2) qkv = LN1(x_w) @ qkv_w + b          [T,128] x [128,384]
    gemm64<128, 384, EPI_NONE><<<dim3(6, MT), 256>>>(aw, qkv_w, qkv_b, nullptr, qkv);
    // 3) windowed attention (+rpb, +shift mask, softmax)
    attn_kernel<<<NWIN / 8, 256>>>(qkv, rpb, o);
    // 4) h2 = x + (o @ proj_w + b), scattered back to original token order
    gemm64<128, 128, EPI_PROJ><<<dim3(2, MT), 256>>>(o, proj_w, proj_b, x, h2);
    // 5) LN2
    ln_kernel<false><<<TOK / 8, 256>>>(h2, g2, b2, ln2);
    // 6) m1 = gelu(ln2 @ w1 + b1)            [T,128] x [128,256]
    gemm64<128, 256, EPI_GELU><<<dim3(4, MT), 256>>>(ln2, w1, bb1, nullptr, m1);
    // 7) out = h2 + (m1 @ w2 + b2)           [T,256] x [256,128]
    gemm64<256, 128, EPI_SKIP><<<dim3(2, MT), 256>>>(m1, w2, bb2, h2, out);
}

// round 2
// speedup vs baseline: 1.1989x; 1.1989x over previous
#include <cuda_runtime.h>
#include <math.h>

// ---------------------------------------------------------------------------
// Swin block: B=32, H=W=128, C=128, WS=2, SS=1, NH=8, HD=16
// ---------------------------------------------------------------------------

#define TOK   524288
#define NWIN  131072

__device__ float g_aw [(size_t)TOK * 128];
__device__ float g_qkv[(size_t)TOK * 384];
__device__ float g_o  [(size_t)TOK * 128];
__device__ float g_h2 [(size_t)TOK * 128];
__device__ float g_ln2[(size_t)TOK * 128];
__device__ float g_m1 [(size_t)TOK * 256];

// packed f32x2 helpers (sm_100+)
#define PACK2(u, x, y) asm("mov.b64 %0, {%1,%2};" : "=l"(u) : "f"(x), "f"(y))
#define FMA2(d, a, b)  asm("fma.rn.f32x2 %0, %1, %2, %0;" : "+l"(d) : "l"(a), "l"(b))
#define UNPK(x, y, u)  asm("mov.b64 {%0,%1}, %2;" : "=f"(x), "=f"(y) : "l"(u))

__device__ __forceinline__ int orig_of(int r) {
    int win = r >> 2, s = r & 3;
    int b  = win >> 12;
    int w  = win & 4095;
    int wh = w >> 6, ww = w & 63;
    int ii = ((wh << 1) + (s >> 1) + 1) & 127;
    int jj = ((ww << 1) + (s & 1) + 1) & 127;
    return (b << 14) + (ii << 7) + jj;
}

// ---------------------------------------------------------------------------
// LayerNorm over C=128; one warp per token.
// ---------------------------------------------------------------------------
template <bool GATHER>
__global__ __launch_bounds__(256) void ln_kernel(
    const float* __restrict__ in, const float* __restrict__ gamma,
    const float* __restrict__ beta, float* __restrict__ out)
{
    int row  = (blockIdx.x * 256 + threadIdx.x) >> 5;
    int lane = threadIdx.x & 31;
    int src  = GATHER ? orig_of(row) : row;

    float4 v = *(const float4*)(in + (size_t)src * 128 + lane * 4);
    float s = v.x + v.y + v.z + v.w;
    float q = v.x * v.x + v.y * v.y + v.z * v.z + v.w * v.w;
#pragma unroll
    for (int off = 16; off; off >>= 1) {
        s += __shfl_xor_sync(0xffffffffu, s, off);
        q += __shfl_xor_sync(0xffffffffu, q, off);
    }
    float mean = s * (1.0f / 128.0f);
    float var  = q * (1.0f / 128.0f) - mean * mean;
    float rstd = rsqrtf(var + 1e-5f);

    float4 g = *(const float4*)(gamma + lane * 4);
    float4 b = *(const float4*)(beta  + lane * 4);
    float4 o;
    o.x = (v.x - mean) * rstd * g.x + b.x;
    o.y = (v.y - mean) * rstd * g.y + b.y;
    o.z = (v.z - mean) * rstd * g.z + b.z;
    o.w = (v.w - mean) * rstd * g.w + b.w;
    *(float4*)(out + (size_t)row * 128 + lane * 4) = o;
}

// ---------------------------------------------------------------------------
// 128x128-tile SGEMM, 256 threads, 8x8 micro-tile, f32x2 packed FMA.
// B operands loaded from smem as ulonglong2 (no packs); A splats via mov.b64.
// Per-thread columns are tx*4 .. tx*4+3 and 64+tx*4 .. 64+tx*4+3 so each B
// LDS.128 covers a contiguous 256B span (full bank utilization).
// ---------------------------------------------------------------------------
enum { EPI_NONE = 0, EPI_PROJ = 1, EPI_GELU = 2, EPI_SKIP = 3 };

template <int K, int N, int EPI>
__global__ __launch_bounds__(256) void gemm128(
    const float* __restrict__ A, const float* __restrict__ Bw,
    const float* __restrict__ bias, const float* __restrict__ skip,
    float* __restrict__ out)
{
    __shared__ float AsT[32][132];   // [k][row], padded; rows 16B-aligned (528B)
    __shared__ float Bs [32][128];   // [k][col]

    const int tid = threadIdx.x;
    const int tx = tid & 15, ty = tid >> 4;
    const int r0  = ty << 3;            // 8 rows
    const int ca  = tx << 2;            // cols ca..ca+3 and ca+64..ca+67
    const int rowBase = blockIdx.y << 7;
    const int n0      = blockIdx.x << 7;

    // loader indices (fully coalesced: 8 lanes cover one 128B row segment)
    const int alr = (tid >> 3);         // + rep*32 : A row within tile
    const int alk = (tid & 7) << 2;     // A col within 32-wide k-chunk
    const int blk = (tid >> 3);         // B k-row within chunk
    const int bln = (tid & 7) << 2;     // + q*32 : B col

    unsigned long long acc[8][4];
#pragma unroll
    for (int i = 0; i < 8; i++)
#pragma unroll
        for (int j = 0; j < 4; j++) acc[i][j] = 0ull;

    const int KCH = K / 32;
#pragma unroll
    for (int kc = 0; kc < KCH; kc++) {
        // global loads (regs) before sync
        float4 av[4], bv[4];
#pragma unroll
        for (int rep = 0; rep < 4; rep++)
            av[rep] = *(const float4*)(A + (size_t)(rowBase + alr + rep * 32) * K
                                         + kc * 32 + alk);
#pragma unroll
        for (int q = 0; q < 4; q++)
            bv[q] = *(const float4*)(Bw + (size_t)(kc * 32 + blk) * N
                                        + n0 + bln + q * 32);
        __syncthreads();   // previous compute done
#pragma unroll
        for (int rep = 0; rep < 4; rep++) {
            int rr = alr + rep * 32;
            AsT[alk + 0][rr] = av[rep].x;
            AsT[alk + 1][rr] = av[rep].y;
            AsT[alk + 2][rr] = av[rep].z;
            AsT[alk + 3][rr] = av[rep].w;
        }
#pragma unroll
        for (int q = 0; q < 4; q++)
            *(float4*)&Bs[blk][bln + q * 32] = bv[q];
        __syncthreads();   // smem ready

#pragma unroll
        for (int kk = 0; kk < 32; kk++) {
            ulonglong2 b0 = *(const ulonglong2*)&Bs[kk][ca];        // cols ca..ca+3
            ulonglong2 b1 = *(const ulonglong2*)&Bs[kk][ca + 64];   // cols +64
            float4 a0 = *(const float4*)&AsT[kk][r0];
            float4 a1 = *(const float4*)&AsT[kk][r0 + 4];
            unsigned long long ad;
            PACK2(ad, a0.x, a0.x);
            FMA2(acc[0][0], ad, b0.x); FMA2(acc[0][1], ad, b0.y);
            FMA2(acc[0][2], ad, b1.x); FMA2(acc[0][3], ad, b1.y);
            PACK2(ad, a0.y, a0.y);
            FMA2(acc[1][0], ad, b0.x); FMA2(acc[1][1], ad, b0.y);
            FMA2(acc[1][2], ad, b1.x); FMA2(acc[1][3], ad, b1.y);
            PACK2(ad, a0.z, a0.z);
            FMA2(acc[2][0], ad, b0.x); FMA2(acc[2][1], ad, b0.y);
            FMA2(acc[2][2], ad, b1.x); FMA2(acc[2][3], ad, b1.y);
            PACK2(ad, a0.w, a0.w);
            FMA2(acc[3][0], ad, b0.x); FMA2(acc[3][1], ad, b0.y);
            FMA2(acc[3][2], ad, b1.x); FMA2(acc[3][3], ad, b1.y);
            PACK2(ad, a1.x, a1.x);
            FMA2(acc[4][0], ad, b0.x); FMA2(acc[4][1], ad, b0.y);
            FMA2(acc[4][2], ad, b1.x); FMA2(acc[4][3], ad, b1.y);
            PACK2(ad, a1.y, a1.y);
            FMA2(acc[5][0], ad, b0.x); FMA2(acc[5][1], ad, b0.y);
            FMA2(acc[5][2], ad, b1.x); FMA2(acc[5][3], ad, b1.y);
            PACK2(ad, a1.z, a1.z);
            FMA2(acc[6][0], ad, b0.x); FMA2(acc[6][1], ad, b0.y);
            FMA2(acc[6][2], ad, b1.x); FMA2(acc[6][3], ad, b1.y);
            PACK2(ad, a1.w, a1.w);
            FMA2(acc[7][0], ad, b0.x); FMA2(acc[7][1], ad, b0.y);
            FMA2(acc[7][2], ad, b1.x); FMA2(acc[7][3], ad, b1.y);
        }
    }

    // epilogue: 8 rows x (4 + 4) cols
#pragma unroll
    for (int i = 0; i < 8; i++) {
        int gr = rowBase + r0 + i;
        size_t outRow = (EPI == EPI_PROJ) ? (size_t)orig_of(gr) : (size_t)gr;
        float v[8];
        UNPK(v[0], v[1], acc[i][0]);
        UNPK(v[2], v[3], acc[i][1]);
        UNPK(v[4], v[5], acc[i][2]);
        UNPK(v[6], v[7], acc[i][3]);
#pragma unroll
        for (int half = 0; half < 2; half++) {
            int colBase = n0 + ca + half * 64;
            float4 r;
            float* pr = &r.x;
#pragma unroll
            for (int j = 0; j < 4; j++) {
                float x = v[half * 4 + j] + bias[colBase + j];
                if (EPI == EPI_GELU) x = x * normcdff(x);
                if (EPI == EPI_PROJ || EPI == EPI_SKIP)
                    x += skip[outRow * N + colBase + j];
                pr[j] = x;
            }
            *(float4*)(out + outRow * (size_t)N + colBase) = r;
        }
    }
}

// ---------------------------------------------------------------------------
// Windowed attention: one warp per window; lane = head*4 + query_token.
// ---------------------------------------------------------------------------
__global__ __launch_bounds__(256) void attn_kernel(
    const float* __restrict__ qkv, const float* __restrict__ rpb,
    float* __restrict__ o)
{
    int warp = (blockIdx.x * 256 + threadIdx.x) >> 5;
    int lane = threadIdx.x & 31;
    int h = lane >> 2, i = lane & 3;

    int w  = warp & 4095;
    bool mr = ((w >> 6) == 63);
    bool mc = ((w & 63) == 63);

    const float* base = qkv + (size_t)warp * (4 * 384);

    float q[16];
    const float* qp = base + i * 384 + h * 16;
#pragma unroll
    for (int d4 = 0; d4 < 4; d4++) {
        float4 t = *(const float4*)(qp + d4 * 4);
        q[d4 * 4 + 0] = t.x; q[d4 * 4 + 1] = t.y;
        q[d4 * 4 + 2] = t.z; q[d4 * 4 + 3] = t.w;
    }

    int dy1 = i >> 1, dx1 = i & 1;
    float s[4];
#pragma unroll
    for (int j = 0; j < 4; j++) {
        const float* kp = base + j * 384 + 128 + h * 16;
        float acc = 0.0f;
#pragma unroll
        for (int d4 = 0; d4 < 4; d4++) {
            float4 t = *(const float4*)(kp + d4 * 4);
            acc += q[d4 * 4 + 0] * t.x + q[d4 * 4 + 1] * t.y
                 + q[d4 * 4 + 2] * t.z + q[d4 * 4 + 3] * t.w;
        }
        int dy2 = j >> 1, dx2 = j & 1;
        bool ok = (!mr || dy1 == dy2) && (!mc || dx1 == dx2);
        int rpi = (dy1 - dy2 + 1) * 3 + (dx1 - dx2 + 1);
        s[j] = acc * 0.25f + rpb[rpi * 8 + h] + (ok ? 0.0f : -100.0f);
    }

    float mx = fmaxf(fmaxf(s[0], s[1]), fmaxf(s[2], s[3]));
    float p[4], sum = 0.0f;
#pragma unroll
    for (int j = 0; j < 4; j++) { p[j] = expf(s[j] - mx); sum += p[j]; }
    float inv = 1.0f / sum;

    float ov[16];
#pragma unroll
    for (int d = 0; d < 16; d++) ov[d] = 0.0f;
#pragma unroll
    for (int j = 0; j < 4; j++) {
        const float* vp = base + j * 384 + 256 + h * 16;
        float pj = p[j] * inv;
#pragma unroll
        for (int d4 = 0; d4 < 4; d4++) {
            float4 t = *(const float4*)(vp + d4 * 4);
            ov[d4 * 4 + 0] += pj * t.x; ov[d4 * 4 + 1] += pj * t.y;
            ov[d4 * 4 + 2] += pj * t.z; ov[d4 * 4 + 3] += pj * t.w;
        }
    }

    float* op = o + (size_t)(warp * 4 + i) * 128 + h * 16;
#pragma unroll
    for (int d4 = 0; d4 < 4; d4++) {
        float4 t;
        t.x = ov[d4 * 4 + 0]; t.y = ov[d4 * 4 + 1];
        t.z = ov[d4 * 4 + 2]; t.w = ov[d4 * 4 + 3];
        *(float4*)(op + d4 * 4) = t;
    }
}

// ---------------------------------------------------------------------------
extern "C" void kernel_launch(void* const* d_in, const int* in_sizes, int n_in,
                              void* d_out, int out_size)
{
    const float* x      = (const float*)d_in[0];
    const float* qkv_w  = (const float*)d_in[1];
    const float* qkv_b  = (const float*)d_in[2];
    const float* proj_w = (const float*)d_in[3];
    const float* proj_b = (const float*)d_in[4];
    const float* rpb    = (const float*)d_in[5];
    const float* g1     = (const float*)d_in[6];
    const float* b1     = (const float*)d_in[7];
    const float* g2     = (const float*)d_in[8];
    const float* b2     = (const float*)d_in[9];
    const float* w1     = (const float*)d_in[10];
    const float* bb1    = (const float*)d_in[11];
    const float* w2     = (const float*)d_in[12];
    const float* bb2    = (const float*)d_in[13];
    float* out = (float*)d_out;

    float *aw, *qkv, *o, *h2, *ln2, *m1;
    cudaGetSymbolAddress((void**)&aw,  g_aw);
    cudaGetSymbolAddress((void**)&qkv, g_qkv);
    cudaGetSymbolAddress((void**)&o,   g_o);
    cudaGetSymbolAddress((void**)&h2,  g_h2);
    cudaGetSymbolAddress((void**)&ln2, g_ln2);
    cudaGetSymbolAddress((void**)&m1,  g_m1);

    const int MT = TOK / 128; // 4096 M-tiles

    ln_kernel<true><<<TOK / 8, 256>>>(x, g1, b1, aw);
    gemm128<128, 384, EPI_NONE><<<dim3(3, MT), 256>>>(aw, qkv_w, qkv_b, nullptr, qkv);
    attn_kernel<<<NWIN / 8, 256>>>(qkv, rpb, o);
    gemm128<128, 128, EPI_PROJ><<<dim3(1, MT), 256>>>(o, proj_w, proj_b, x, h2);
    ln_kernel<false><<<TOK / 8, 256>>>(h2, g2, b2, ln2);
    gemm128<128, 256, EPI_GELU><<<dim3(2, MT), 256>>>(ln2, w1, bb1, nullptr, m1);
    gemm128<256, 128, EPI_SKIP><<<dim3(1, MT), 256>>>(m1, w2, bb2, h2, out);
}

// round 4
// speedup vs baseline: 2.2301x; 1.8601x over previous
#include <cuda_runtime.h>
#include <cuda_bf16.h>
#include <math.h>
#include <stdint.h>

// ---------------------------------------------------------------------------
// Swin block: B=32, H=W=128, C=128, WS=2, SS=1, NH=8, HD=16
// GEMMs: warp-level mma.sync bf16 (hi/lo x3 emulated fp32) — baseline PTX,
// works on the harness's compute_103 target (tcgen05 needs sm_103a, rejected).
// ---------------------------------------------------------------------------

#define TOK   524288
#define NWIN  131072

typedef __nv_bfloat16 bf16;

// scratch
__device__ bf16  g_awhi[(size_t)TOK * 128];
__device__ bf16  g_awlo[(size_t)TOK * 128];
__device__ float g_qkv [(size_t)TOK * 384];
__device__ bf16  g_ohi [(size_t)TOK * 128];
__device__ bf16  g_olo [(size_t)TOK * 128];
__device__ float g_h2  [(size_t)TOK * 128];
__device__ bf16  g_l2hi[(size_t)TOK * 128];
__device__ bf16  g_l2lo[(size_t)TOK * 128];
__device__ bf16  g_m1hi[(size_t)TOK * 256];
__device__ bf16  g_m1lo[(size_t)TOK * 256];
// weights transposed to [N,K] + split
__device__ bf16  g_wqh[384 * 128], g_wql[384 * 128];
__device__ bf16  g_wph[128 * 128], g_wpl[128 * 128];
__device__ bf16  g_w1h[256 * 128], g_w1l[256 * 128];
__device__ bf16  g_w2h[128 * 256], g_w2l[128 * 256];

// ---------------------------------------------------------------------------
__device__ __forceinline__ uint32_t smem_u32(const void* p) {
    uint32_t a;
    asm("{ .reg .u64 t; cvta.to.shared.u64 t, %1; cvt.u32.u64 %0, t; }"
        : "=r"(a) : "l"(p));
    return a;
}

#define SWZ128(o) ((o) ^ (((o) >> 3) & 0x70))

#define CP_ASYNC16(dst, src) \
    asm volatile("cp.async.cg.shared.global [%0], [%1], 16;" \
                 :: "r"(dst), "l"(src) : "memory")
#define CP_COMMIT()   asm volatile("cp.async.commit_group;" ::: "memory")
#define CP_WAIT(n)    asm volatile("cp.async.wait_group %0;" :: "n"(n) : "memory")

__device__ __forceinline__ void ldsm4(uint32_t r[4], uint32_t addr) {
    asm volatile("ldmatrix.sync.aligned.m8n8.x4.shared.b16 {%0,%1,%2,%3}, [%4];"
                 : "=r"(r[0]), "=r"(r[1]), "=r"(r[2]), "=r"(r[3]) : "r"(addr));
}

__device__ __forceinline__ void mma_bf16(float4& d, const uint32_t a[4],
                                         const uint32_t b[2]) {
    asm volatile(
        "mma.sync.aligned.m16n8k16.row.col.f32.bf16.bf16.f32 "
        "{%0,%1,%2,%3}, {%4,%5,%6,%7}, {%8,%9}, {%0,%1,%2,%3};"
        : "+f"(d.x), "+f"(d.y), "+f"(d.z), "+f"(d.w)
        : "r"(a[0]), "r"(a[1]), "r"(a[2]), "r"(a[3]), "r"(b[0]), "r"(b[1]));
}

// ---------------------------------------------------------------------------
__device__ __forceinline__ int orig_of(int r) {
    int win = r >> 2, s = r & 3;
    int b  = win >> 12;
    int w  = win & 4095;
    int wh = w >> 6, ww = w & 63;
    int ii = ((wh << 1) + (s >> 1) + 1) & 127;
    int jj = ((ww << 1) + (s & 1) + 1) & 127;
    return (b << 14) + (ii << 7) + jj;
}

__device__ __forceinline__ uint32_t pk2(float a, float b) {
    __nv_bfloat162 t = __floats2bfloat162_rn(a, b);
    return *(uint32_t*)&t;
}
__device__ __forceinline__ float bhi(float v) {
    return __bfloat162float(__float2bfloat16(v));
}

// ---------------------------------------------------------------------------
// LayerNorm; one warp per token; writes bf16 hi/lo split
// ---------------------------------------------------------------------------
template <bool GATHER>
__global__ __launch_bounds__(256) void ln_kernel(
    const float* __restrict__ in, const float* __restrict__ gamma,
    const float* __restrict__ beta, bf16* __restrict__ ohi,
    bf16* __restrict__ olo)
{
    int row  = (blockIdx.x * 256 + threadIdx.x) >> 5;
    int lane = threadIdx.x & 31;
    int src  = GATHER ? orig_of(row) : row;

    float4 v = *(const float4*)(in + (size_t)src * 128 + lane * 4);
    float s = v.x + v.y + v.z + v.w;
    float q = v.x * v.x + v.y * v.y + v.z * v.z + v.w * v.w;
#pragma unroll
    for (int off = 16; off; off >>= 1) {
        s += __shfl_xor_sync(0xffffffffu, s, off);
        q += __shfl_xor_sync(0xffffffffu, q, off);
    }
    float mean = s * (1.0f / 128.0f);
    float var  = q * (1.0f / 128.0f) - mean * mean;
    float rstd = rsqrtf(var + 1e-5f);

    float4 g = *(const float4*)(gamma + lane * 4);
    float4 b = *(const float4*)(beta  + lane * 4);
    float o0 = (v.x - mean) * rstd * g.x + b.x;
    float o1 = (v.y - mean) * rstd * g.y + b.y;
    float o2 = (v.z - mean) * rstd * g.z + b.z;
    float o3 = (v.w - mean) * rstd * g.w + b.w;
    float h0 = bhi(o0), h1 = bhi(o1), h2 = bhi(o2), h3 = bhi(o3);
    uint2 uh = make_uint2(pk2(h0, h1), pk2(h2, h3));
    uint2 ul = make_uint2(pk2(o0 - h0, o1 - h1), pk2(o2 - h2, o3 - h3));
    ((uint2*)ohi)[(size_t)row * 32 + lane] = uh;
    ((uint2*)olo)[(size_t)row * 32 + lane] = ul;
}

// ---------------------------------------------------------------------------
// Weight transpose + split: w[K,N] fp32 -> hi/lo [N,K] bf16
// ---------------------------------------------------------------------------
__global__ void wconv(const float* __restrict__ w, int K, int N,
                      bf16* __restrict__ hi, bf16* __restrict__ lo)
{
    int idx = blockIdx.x * 256 + threadIdx.x;
    if (idx >= N * K) return;
    int n = idx / K, k = idx - n * K;
    float v = w[(size_t)k * N + n];
    float h = bhi(v);
    hi[idx] = __float2bfloat16(v);
    lo[idx] = __float2bfloat16(v - h);
}

// ---------------------------------------------------------------------------
// Warp-MMA GEMM: CTA 128x128, 8 warps (64x32 each), K-chunk 64, 2-stage
// cp.async pipeline.  D = Ahi*Bhi + Ahi*Blo + Alo*Bhi  (fp32 accum).
// A: [M,K] bf16 row-major (hi/lo).  B: [N,K] bf16 row-major (hi/lo).
// ---------------------------------------------------------------------------
enum { EPI_NONE = 0, EPI_PROJ = 1, EPI_GELU = 2, EPI_SKIP = 3 };

#define STAGE_BYTES 65536     // Ahi 16K | Alo 16K | Bhi 16K | Blo 16K
#define SMEM_TOTAL  131072

template <int K, int N, int EPI>
__global__ __launch_bounds__(256) void wgemm(
    const bf16* __restrict__ Ahi, const bf16* __restrict__ Alo,
    const bf16* __restrict__ Bhi, const bf16* __restrict__ Blo,
    const float* __restrict__ bias, const float* __restrict__ skip,
    float* __restrict__ out, bf16* __restrict__ outhi, bf16* __restrict__ outlo)
{
    extern __shared__ char smem[];
    const uint32_t sb = smem_u32(smem);
    const int tid  = threadIdx.x;
    const int lane = tid & 31, wid = tid >> 5;
    const int warp_m = wid >> 2, warp_n = wid & 3;  // 2 x 4 warp grid
    const int rowBase = blockIdx.y << 7;
    const int n0      = blockIdx.x << 7;
    constexpr int NCH = K / 64;

    float4 acc[4][4];
#pragma unroll
    for (int i = 0; i < 4; i++)
#pragma unroll
        for (int j = 0; j < 4; j++)
            acc[i][j] = make_float4(0.f, 0.f, 0.f, 0.f);

    // ---- cp.async stage loader -------------------------------------------
    const int lrow = tid >> 3;          // 0..31 (+32*it)
    const int lc16 = tid & 7;           // 16B column within 128B row
    auto issue = [&](int kc, int buf) {
        const bf16* srcs[4] = {
            Ahi + (size_t)rowBase * K + kc * 64,
            Alo + (size_t)rowBase * K + kc * 64,
            Bhi + (size_t)n0 * K + kc * 64,
            Blo + (size_t)n0 * K + kc * 64 };
        const uint32_t base = sb + buf * STAGE_BYTES;
#pragma unroll
        for (int part = 0; part < 4; part++) {
#pragma unroll
            for (int it = 0; it < 4; it++) {
                int row = lrow + it * 32;
                const bf16* src = srcs[part] + (size_t)row * K + lc16 * 8;
                uint32_t dst = base + part * 16384
                             + SWZ128((uint32_t)(row * 128 + lc16 * 16));
                CP_ASYNC16(dst, src);
            }
        }
        CP_COMMIT();
    };

    // ---- per-lane ldmatrix address components ----------------------------
    const int arow = warp_m * 64 + (lane & 15);      // A row (+ mt*16)
    const int akb  = (lane >> 4) * 8;                // A k offset (0/8)
    const int brow = warp_n * 32 + ((lane >> 4) & 1) * 8 + (lane & 7); // + i*16
    const int bkb  = ((lane >> 3) & 1) * 8;          // B k offset (0/8)

    issue(0, 0);

    for (int kc = 0; kc < NCH; kc++) {
        if (kc + 1 < NCH) { issue(kc + 1, (kc + 1) & 1); CP_WAIT(1); }
        else             { CP_WAIT(0); }
        __syncthreads();

        const uint32_t stage = sb + (kc & 1) * STAGE_BYTES;
#pragma unroll
        for (int ks = 0; ks < 4; ks++) {
            const int k0 = ks * 16;
            uint32_t bh[2][4], bl[2][4];
#pragma unroll
            for (int i = 0; i < 2; i++) {
                uint32_t boff = SWZ128((uint32_t)((brow + i * 16) * 128
                                                  + (k0 + bkb) * 2));
                ldsm4(bh[i], stage + 32768 + boff);
                ldsm4(bl[i], stage + 49152 + boff);
            }
#pragma unroll
            for (int mt = 0; mt < 4; mt++) {
                uint32_t aoff = SWZ128((uint32_t)((arow + mt * 16) * 128
                                                  + (k0 + akb) * 2));
                uint32_t ah[4], al[4];
                ldsm4(ah, stage + aoff);
                ldsm4(al, stage + 16384 + aoff);
#pragma unroll
                for (int nt = 0; nt < 4; nt++) {
                    const uint32_t* ph = &bh[nt >> 1][(nt & 1) * 2];
                    const uint32_t* pl = &bl[nt >> 1][(nt & 1) * 2];
                    mma_bf16(acc[mt][nt], ah, ph);
                    mma_bf16(acc[mt][nt], ah, pl);
                    mma_bf16(acc[mt][nt], al, ph);
                }
            }
        }
        __syncthreads();
    }

    // ---- epilogue ---------------------------------------------------------
    const int r4 = lane >> 2;
    const int c2 = (lane & 3) * 2;
#pragma unroll
    for (int mt = 0; mt < 4; mt++) {
#pragma unroll
        for (int half = 0; half < 2; half++) {
            const int gr = rowBase + warp_m * 64 + mt * 16 + r4 + half * 8;
            const size_t outRow = (EPI == EPI_PROJ) ? (size_t)orig_of(gr)
                                                    : (size_t)gr;
#pragma unroll
            for (int nt = 0; nt < 4; nt++) {
                const int col = n0 + warp_n * 32 + nt * 8 + c2;
                float v0 = half ? acc[mt][nt].z : acc[mt][nt].x;
                float v1 = half ? acc[mt][nt].w : acc[mt][nt].y;
                v0 += bias[col];
                v1 += bias[col + 1];
                if (EPI == EPI_GELU) {
                    v0 = v0 * normcdff(v0);
                    v1 = v1 * normcdff(v1);
                    float h0 = bhi(v0), h1 = bhi(v1);
                    *(uint32_t*)(outhi + outRow * N + col) = pk2(h0, h1);
                    *(uint32_t*)(outlo + outRow * N + col) = pk2(v0 - h0, v1 - h1);
                } else {
                    if (EPI == EPI_PROJ || EPI == EPI_SKIP) {
                        const float2 sk = *(const float2*)(skip + outRow * N + col);
                        v0 += sk.x; v1 += sk.y;
                    }
                    float2 r = make_float2(v0, v1);
                    *(float2*)(out + outRow * N + col) = r;
                }
            }
        }
    }
}

// ---------------------------------------------------------------------------
// Windowed attention: one warp per window; writes hi/lo split output.
// ---------------------------------------------------------------------------
__global__ __launch_bounds__(256) void attn_kernel(
    const float* __restrict__ qkv, const float* __restrict__ rpb,
    bf16* __restrict__ ohi, bf16* __restrict__ olo)
{
    int warp = (blockIdx.x * 256 + threadIdx.x) >> 5;
    int lane = threadIdx.x & 31;
    int h = lane >> 2, i = lane & 3;

    int w  = warp & 4095;
    bool mr = ((w >> 6) == 63);
    bool mc = ((w & 63) == 63);

    const float* base = qkv + (size_t)warp * (4 * 384);

    float q[16];
    const float* qp = base + i * 384 + h * 16;
#pragma unroll
    for (int d4 = 0; d4 < 4; d4++) {
        float4 t = *(const float4*)(qp + d4 * 4);
        q[d4 * 4 + 0] = t.x; q[d4 * 4 + 1] = t.y;
        q[d4 * 4 + 2] = t.z; q[d4 * 4 + 3] = t.w;
    }

    int dy1 = i >> 1, dx1 = i & 1;
    float s[4];
#pragma unroll
    for (int j = 0; j < 4; j++) {
        const float* kp = base + j * 384 + 128 + h * 16;
        float acc = 0.0f;
#pragma unroll
        for (int d4 = 0; d4 < 4; d4++) {
            float4 t = *(const float4*)(kp + d4 * 4);
            acc += q[d4 * 4 + 0] * t.x + q[d4 * 4 + 1] * t.y
                 + q[d4 * 4 + 2] * t.z + q[d4 * 4 + 3] * t.w;
        }
        int dy2 = j >> 1, dx2 = j & 1;
        bool ok = (!mr || dy1 == dy2) && (!mc || dx1 == dx2);
        int rpi = (dy1 - dy2 + 1) * 3 + (dx1 - dx2 + 1);
        s[j] = acc * 0.25f + rpb[rpi * 8 + h] + (ok ? 0.0f : -100.0f);
    }

    float mx = fmaxf(fmaxf(s[0], s[1]), fmaxf(s[2], s[3]));
    float p[4], sum = 0.0f;
#pragma unroll
    for (int j = 0; j < 4; j++) { p[j] = expf(s[j] - mx); sum += p[j]; }
    float inv = 1.0f / sum;

    float ov[16];
#pragma unroll
    for (int d = 0; d < 16; d++) ov[d] = 0.0f;
#pragma unroll
    for (int j = 0; j < 4; j++) {
        const float* vp = base + j * 384 + 256 + h * 16;
        float pj = p[j] * inv;
#pragma unroll
        for (int d4 = 0; d4 < 4; d4++) {
            float4 t = *(const float4*)(vp + d4 * 4);
            ov[d4 * 4 + 0] += pj * t.x; ov[d4 * 4 + 1] += pj * t.y;
            ov[d4 * 4 + 2] += pj * t.z; ov[d4 * 4 + 3] += pj * t.w;
        }
    }

    float hv[16];
#pragma unroll
    for (int d = 0; d < 16; d++) hv[d] = bhi(ov[d]);
    size_t u4 = ((size_t)(warp * 4 + i) * 128 + h * 16) >> 3;
    uint4 uh0 = make_uint4(pk2(hv[0], hv[1]), pk2(hv[2], hv[3]),
                           pk2(hv[4], hv[5]), pk2(hv[6], hv[7]));
    uint4 uh1 = make_uint4(pk2(hv[8], hv[9]), pk2(hv[10], hv[11]),
                           pk2(hv[12], hv[13]), pk2(hv[14], hv[15]));
    uint4 ul0 = make_uint4(pk2(ov[0] - hv[0], ov[1] - hv[1]), pk2(ov[2] - hv[2], ov[3] - hv[3]),
                           pk2(ov[4] - hv[4], ov[5] - hv[5]), pk2(ov[6] - hv[6], ov[7] - hv[7]));
    uint4 ul1 = make_uint4(pk2(ov[8] - hv[8], ov[9] - hv[9]), pk2(ov[10] - hv[10], ov[11] - hv[11]),
                           pk2(ov[12] - hv[12], ov[13] - hv[13]), pk2(ov[14] - hv[14], ov[15] - hv[15]));
    ((uint4*)ohi)[u4 + 0] = uh0; ((uint4*)ohi)[u4 + 1] = uh1;
    ((uint4*)olo)[u4 + 0] = ul0; ((uint4*)olo)[u4 + 1] = ul1;
}

// ---------------------------------------------------------------------------
extern "C" void kernel_launch(void* const* d_in, const int* in_sizes, int n_in,
                              void* d_out, int out_size)
{
    const float* x      = (const float*)d_in[0];
    const float* qkv_w  = (const float*)d_in[1];
    const float* qkv_b  = (const float*)d_in[2];
    const float* proj_w = (const float*)d_in[3];
    const float* proj_b = (const float*)d_in[4];
    const float* rpb    = (const float*)d_in[5];
    const float* g1     = (const float*)d_in[6];
    const float* b1     = (const float*)d_in[7];
    const float* g2     = (const float*)d_in[8];
    const float* b2     = (const float*)d_in[9];
    const float* w1     = (const float*)d_in[10];
    const float* bb1    = (const float*)d_in[11];
    const float* w2     = (const float*)d_in[12];
    const float* bb2    = (const float*)d_in[13];
    float* out = (float*)d_out;

    bf16 *awhi, *awlo, *ohi, *olo, *l2hi, *l2lo, *m1hi, *m1lo;
    bf16 *wqh, *wql, *wph, *wpl, *w1h, *w1l, *w2h, *w2l;
    float *qkv, *h2;
    cudaGetSymbolAddress((void**)&awhi, g_awhi);
    cudaGetSymbolAddress((void**)&awlo, g_awlo);
    cudaGetSymbolAddress((void**)&qkv,  g_qkv);
    cudaGetSymbolAddress((void**)&ohi,  g_ohi);
    cudaGetSymbolAddress((void**)&olo,  g_olo);
    cudaGetSymbolAddress((void**)&h2,   g_h2);
    cudaGetSymbolAddress((void**)&l2hi, g_l2hi);
    cudaGetSymbolAddress((void**)&l2lo, g_l2lo);
    cudaGetSymbolAddress((void**)&m1hi, g_m1hi);
    cudaGetSymbolAddress((void**)&m1lo, g_m1lo);
    cudaGetSymbolAddress((void**)&wqh,  g_wqh);
    cudaGetSymbolAddress((void**)&wql,  g_wql);
    cudaGetSymbolAddress((void**)&wph,  g_wph);
    cudaGetSymbolAddress((void**)&wpl,  g_wpl);
    cudaGetSymbolAddress((void**)&w1h,  g_w1h);
    cudaGetSymbolAddress((void**)&w1l,  g_w1l);
    cudaGetSymbolAddress((void**)&w2h,  g_w2h);
    cudaGetSymbolAddress((void**)&w2l,  g_w2l);

    cudaFuncSetAttribute(wgemm<128, 384, EPI_NONE>, cudaFuncAttributeMaxDynamicSharedMemorySize, SMEM_TOTAL);
    cudaFuncSetAttribute(wgemm<128, 128, EPI_PROJ>, cudaFuncAttributeMaxDynamicSharedMemorySize, SMEM_TOTAL);
    cudaFuncSetAttribute(wgemm<128, 256, EPI_GELU>, cudaFuncAttributeMaxDynamicSharedMemorySize, SMEM_TOTAL);
    cudaFuncSetAttribute(wgemm<256, 128, EPI_SKIP>, cudaFuncAttributeMaxDynamicSharedMemorySize, SMEM_TOTAL);

    const int MT = TOK / 128; // 4096 M-tiles

    // weight transpose+split (tiny)
    wconv<<<(384 * 128 + 255) / 256, 256>>>(qkv_w,  128, 384, wqh, wql);
    wconv<<<(128 * 128 + 255) / 256, 256>>>(proj_w, 128, 128, wph, wpl);
    wconv<<<(256 * 128 + 255) / 256, 256>>>(w1,     128, 256, w1h, w1l);
    wconv<<<(128 * 256 + 255) / 256, 256>>>(w2,     256, 128, w2h, w2l);

    // 1) LN1 + shift + window gather -> bf16 hi/lo
    ln_kernel<true><<<TOK / 8, 256>>>(x, g1, b1, awhi, awlo);
    // 2) qkv = aw @ qkv_w + b (fp32 out)
    wgemm<128, 384, EPI_NONE><<<dim3(3, MT), 256, SMEM_TOTAL>>>(
        awhi, awlo, wqh, wql, qkv_b, nullptr, qkv, nullptr, nullptr);
    // 3) attention -> o hi/lo
    attn_kernel<<<NWIN / 8, 256>>>(qkv, rpb, ohi, olo);
    // 4) h2 = x + (o @ proj_w + b), scattered to original order
    wgemm<128, 128, EPI_PROJ><<<dim3(1, MT), 256, SMEM_TOTAL>>>(
        ohi, olo, wph, wpl, proj_b, x, h2, nullptr, nullptr);
    // 5) LN2 -> bf16 hi/lo
    ln_kernel<false><<<TOK / 8, 256>>>(h2, g2, b2, l2hi, l2lo);
    // 6) m1 = gelu(ln2 @ w1 + b1) -> bf16 hi/lo
    wgemm<128, 256, EPI_GELU><<<dim3(2, MT), 256, SMEM_TOTAL>>>(
        l2hi, l2lo, w1h, w1l, bb1, nullptr, nullptr, m1hi, m1lo);
    // 7) out = h2 + (m1 @ w2 + b2)
    wgemm<256, 128, EPI_SKIP><<<dim3(1, MT), 256, SMEM_TOTAL>>>(
        m1hi, m1lo, w2h, w2l, bb2, h2, out, nullptr, nullptr);
}